// round 12
// baseline (speedup 1.0000x reference)
#include <cuda_runtime.h>
#include <math.h>

// Problem constants
#define NFEAT   256
#define BATCH   8192
#define H1DIM   100
#define H2DIM   50
#define W2SZ    (H2DIM * H1DIM)   // 5000

// Tiling: 128 threads, 2 batch rows per thread -> 256 rows per block
#define THREADS          128
#define RPT              2
#define ROWS_PER_BLOCK   (THREADS * RPT)          // 256
#define ROW_TILES        (BATCH / ROWS_PER_BLOCK) // 32
#define FEATS_PER_CHUNK  8
#define FEAT_CHUNKS      (NFEAT / FEATS_PER_CHUNK) // 32
#define W2_STRIDE        52   // padded [h][o] row: 52*4=208B, 16B-aligned rows

// Per-chunk partial sums (written unconditionally each launch -> deterministic)
__device__ float g_partial[FEAT_CHUNKS][BATCH];

struct SmemBuf {
    float  w2t[H1DIM][W2_STRIDE]; // transposed W2: [h][o], o contiguous for f32x2
    float2 w1b1[H1DIM];           // packed (w1[h], b1[h]) -> one LDS.64 per h
    float  b2[H2DIM];             // 8B-aligned
    float  w3[H2DIM];
};

// ---- f32x2 packed helpers (sm_100+ PTX) ----
__device__ __forceinline__ unsigned long long pack2(float v) {
    unsigned long long r;
    asm("mov.b64 %0, {%1, %1};" : "=l"(r) : "f"(v));
    return r;
}
__device__ __forceinline__ void ffma2(unsigned long long& acc,
                                      unsigned long long a,
                                      unsigned long long b) {
    asm("fma.rn.f32x2 %0, %1, %2, %0;" : "+l"(acc) : "l"(a), "l"(b));
}
__device__ __forceinline__ void unpack2(unsigned long long v, float& lo, float& hi) {
    asm("mov.b64 {%0, %1}, %2;" : "=f"(lo), "=f"(hi) : "l"(v));
}

// Stage one feature's weights into a shared buffer (cooperative, coalesced LDG)
__device__ __forceinline__ void stage(SmemBuf& b,
                                      const float* __restrict__ W1f,
                                      const float* __restrict__ b1f,
                                      const float* __restrict__ W2f,
                                      const float* __restrict__ b2f,
                                      const float* __restrict__ W3f,
                                      int tid)
{
    #pragma unroll 4
    for (int i = tid; i < W2SZ; i += THREADS) {
        int o = i / H1DIM;
        int h = i - o * H1DIM;
        b.w2t[h][o] = W2f[i];
    }
    if (tid < H1DIM) {
        b.w1b1[tid] = make_float2(W1f[tid], b1f[tid]);
    }
    if (tid < H2DIM) {
        b.b2[tid] = b2f[tid];
        b.w3[tid] = W3f[tid];
    }
}

// Evaluate one feature's subnet for TWO batch rows sharing each w2 smem load.
// 2x50 h2 accumulators live as 2x25 packed f32x2 pairs, initialized with b2.
__device__ __forceinline__ void feat_eval2(const SmemBuf& b, float xa, float xb,
                                           float& ra, float& rb)
{
    unsigned long long accA[25], accB[25];
    const unsigned long long* b2p = reinterpret_cast<const unsigned long long*>(b.b2);
    #pragma unroll
    for (int p = 0; p < 25; ++p) { accA[p] = b2p[p]; accB[p] = b2p[p]; }

    #pragma unroll 1
    for (int h = 0; h < H1DIM; ++h) {
        float2 wb = b.w1b1[h];
        float h1a = fmaxf(fmaf(xa, wb.x, wb.y), 0.0f);
        float h1b = fmaxf(fmaf(xb, wb.x, wb.y), 0.0f);
        unsigned long long pa = pack2(h1a);
        unsigned long long pb = pack2(h1b);
        const unsigned long long* w2row =
            reinterpret_cast<const unsigned long long*>(&b.w2t[h][0]);
        #pragma unroll
        for (int p = 0; p < 25; ++p) {
            unsigned long long w = w2row[p];   // one LDS.64, reused twice
            ffma2(accA[p], w, pa);
            ffma2(accB[p], w, pb);
        }
    }

    float sa = 0.0f, sb = 0.0f;
    #pragma unroll
    for (int p = 0; p < 25; ++p) {
        float lo, hi;
        float w3lo = b.w3[2 * p], w3hi = b.w3[2 * p + 1];
        unpack2(accA[p], lo, hi);
        sa = fmaf(fmaxf(lo, 0.0f), w3lo, sa);
        sa = fmaf(fmaxf(hi, 0.0f), w3hi, sa);
        unpack2(accB[p], lo, hi);
        sb = fmaf(fmaxf(lo, 0.0f), w3lo, sb);
        sb = fmaf(fmaxf(hi, 0.0f), w3hi, sb);
    }
    ra = sa; rb = sb;
}

__global__ void __launch_bounds__(THREADS, 3)
nam_main(const float* __restrict__ x,  const float* __restrict__ W1,
         const float* __restrict__ b1, const float* __restrict__ W2,
         const float* __restrict__ b2, const float* __restrict__ W3)
{
    __shared__ SmemBuf sb[2];

    const int tid  = threadIdx.x;
    const int rowA = blockIdx.x * ROWS_PER_BLOCK + tid;           // rows strided by 128
    const int rowB = rowA + THREADS;
    const int f0   = blockIdx.y * FEATS_PER_CHUNK;
    const float* xrowA = x + (long)rowA * NFEAT + f0;
    const float* xrowB = x + (long)rowB * NFEAT + f0;

    // prologue: stage feature f0 into buffer 0
    stage(sb[0], W1 + f0 * H1DIM, b1 + f0 * H1DIM, W2 + (long)f0 * W2SZ,
          b2 + f0 * H2DIM, W3 + f0 * H2DIM, tid);
    __syncthreads();

    float accA = 0.0f, accB = 0.0f;
    #pragma unroll 1
    for (int k = 0; k < FEATS_PER_CHUNK; ++k) {
        // stage next feature into the other buffer (hidden under compute)
        if (k + 1 < FEATS_PER_CHUNK) {
            int f = f0 + k + 1;
            stage(sb[(k + 1) & 1], W1 + f * H1DIM, b1 + f * H1DIM,
                  W2 + (long)f * W2SZ, b2 + f * H2DIM, W3 + f * H2DIM, tid);
        }
        float ra, rb;
        feat_eval2(sb[k & 1], xrowA[k], xrowB[k], ra, rb);
        accA += ra;
        accB += rb;
        __syncthreads();
    }

    g_partial[blockIdx.y][rowA] = accA;
    g_partial[blockIdx.y][rowB] = accB;
}

__global__ void nam_reduce(const float* __restrict__ bias, float* __restrict__ out)
{
    int b = blockIdx.x * 256 + threadIdx.x;
    if (b < BATCH) {
        float s = bias[0];
        #pragma unroll
        for (int c = 0; c < FEAT_CHUNKS; ++c) s += g_partial[c][b];
        out[b] = 1.0f / (1.0f + expf(-s));
    }
}

extern "C" void kernel_launch(void* const* d_in, const int* in_sizes, int n_in,
                              void* d_out, int out_size)
{
    const float* x    = (const float*)d_in[0];  // [8192,256]
    const float* W1   = (const float*)d_in[1];  // [256,100]
    const float* b1   = (const float*)d_in[2];  // [256,100]
    const float* W2   = (const float*)d_in[3];  // [256,50,100]
    const float* b2   = (const float*)d_in[4];  // [256,50]
    const float* W3   = (const float*)d_in[5];  // [256,50]
    const float* bias = (const float*)d_in[6];  // [1]
    float* out = (float*)d_out;                 // [8192]

    dim3 grid(ROW_TILES, FEAT_CHUNKS);
    nam_main<<<grid, THREADS>>>(x, W1, b1, W2, b2, W3);
    nam_reduce<<<BATCH / 256, 256>>>(bias, out);
}

// round 13
// speedup vs baseline: 1.0045x; 1.0045x over previous
#include <cuda_runtime.h>
#include <math.h>

// Problem constants
#define NFEAT   256
#define BATCH   8192
#define H1DIM   100
#define H2DIM   50
#define W2SZ    (H2DIM * H1DIM)   // 5000

// Tiling: 128 threads, 2 batch rows per thread -> 256 rows per block
#define THREADS          128
#define RPT              2
#define ROWS_PER_BLOCK   (THREADS * RPT)          // 256
#define ROW_TILES        (BATCH / ROWS_PER_BLOCK) // 32
#define FEATS_PER_CHUNK  8
#define FEAT_CHUNKS      (NFEAT / FEATS_PER_CHUNK) // 32
#define W2_STRIDE        52   // padded [h][o] row: 52*4=208B, 16B-aligned rows

// Per-chunk partial sums (written unconditionally each launch -> deterministic)
__device__ float g_partial[FEAT_CHUNKS][BATCH];

struct SmemBuf {
    float  w2t[H1DIM][W2_STRIDE]; // transposed W2: [h][o], o contiguous for f32x2
    float2 w1b1[H1DIM];           // packed (w1[h], b1[h]) -> one LDS.64 per h
    float  b2[H2DIM];             // 8B-aligned
    float  w3[H2DIM];
};

// ---- f32x2 packed helpers (sm_100+ PTX) ----
__device__ __forceinline__ unsigned long long pack2(float v) {
    unsigned long long r;
    asm("mov.b64 %0, {%1, %1};" : "=l"(r) : "f"(v));
    return r;
}
__device__ __forceinline__ void ffma2(unsigned long long& acc,
                                      unsigned long long a,
                                      unsigned long long b) {
    asm("fma.rn.f32x2 %0, %1, %2, %0;" : "+l"(acc) : "l"(a), "l"(b));
}
__device__ __forceinline__ void unpack2(unsigned long long v, float& lo, float& hi) {
    asm("mov.b64 {%0, %1}, %2;" : "=f"(lo), "=f"(hi) : "l"(v));
}

// Stage one feature's weights into a shared buffer (cooperative, coalesced LDG)
__device__ __forceinline__ void stage(SmemBuf& b,
                                      const float* __restrict__ W1f,
                                      const float* __restrict__ b1f,
                                      const float* __restrict__ W2f,
                                      const float* __restrict__ b2f,
                                      const float* __restrict__ W3f,
                                      int tid)
{
    #pragma unroll 4
    for (int i = tid; i < W2SZ; i += THREADS) {
        int o = i / H1DIM;
        int h = i - o * H1DIM;
        b.w2t[h][o] = W2f[i];
    }
    if (tid < H1DIM) {
        b.w1b1[tid] = make_float2(W1f[tid], b1f[tid]);
    }
    if (tid < H2DIM) {
        b.b2[tid] = b2f[tid];
        b.w3[tid] = W3f[tid];
    }
}

// Evaluate one feature's subnet for TWO batch rows sharing each w2 smem load.
// 2x50 h2 accumulators live as 2x25 packed f32x2 pairs, initialized with b2.
__device__ __forceinline__ void feat_eval2(const SmemBuf& b, float xa, float xb,
                                           float& ra, float& rb)
{
    unsigned long long accA[25], accB[25];
    const unsigned long long* b2p = reinterpret_cast<const unsigned long long*>(b.b2);
    #pragma unroll
    for (int p = 0; p < 25; ++p) { accA[p] = b2p[p]; accB[p] = b2p[p]; }

    #pragma unroll 1
    for (int h = 0; h < H1DIM; ++h) {
        float2 wb = b.w1b1[h];
        float h1a = fmaxf(fmaf(xa, wb.x, wb.y), 0.0f);
        float h1b = fmaxf(fmaf(xb, wb.x, wb.y), 0.0f);
        unsigned long long pa = pack2(h1a);
        unsigned long long pb = pack2(h1b);
        const unsigned long long* w2row =
            reinterpret_cast<const unsigned long long*>(&b.w2t[h][0]);
        #pragma unroll
        for (int p = 0; p < 25; ++p) {
            unsigned long long w = w2row[p];   // one LDS.64, reused twice
            ffma2(accA[p], w, pa);
            ffma2(accB[p], w, pb);
        }
    }

    float sa = 0.0f, sb = 0.0f;
    #pragma unroll
    for (int p = 0; p < 25; ++p) {
        float lo, hi;
        float w3lo = b.w3[2 * p], w3hi = b.w3[2 * p + 1];
        unpack2(accA[p], lo, hi);
        sa = fmaf(fmaxf(lo, 0.0f), w3lo, sa);
        sa = fmaf(fmaxf(hi, 0.0f), w3hi, sa);
        unpack2(accB[p], lo, hi);
        sb = fmaf(fmaxf(lo, 0.0f), w3lo, sb);
        sb = fmaf(fmaxf(hi, 0.0f), w3hi, sb);
    }
    ra = sa; rb = sb;
}

__global__ void __launch_bounds__(THREADS, 3)
nam_main(const float* __restrict__ x,  const float* __restrict__ W1,
         const float* __restrict__ b1, const float* __restrict__ W2,
         const float* __restrict__ b2, const float* __restrict__ W3)
{
    __shared__ SmemBuf sb[2];

    const int tid  = threadIdx.x;
    const int rowA = blockIdx.x * ROWS_PER_BLOCK + tid;           // rows strided by 128
    const int rowB = rowA + THREADS;
    const int f0   = blockIdx.y * FEATS_PER_CHUNK;
    const float* xrowA = x + (long)rowA * NFEAT + f0;
    const float* xrowB = x + (long)rowB * NFEAT + f0;

    // prologue: stage feature f0 into buffer 0
    stage(sb[0], W1 + f0 * H1DIM, b1 + f0 * H1DIM, W2 + (long)f0 * W2SZ,
          b2 + f0 * H2DIM, W3 + f0 * H2DIM, tid);
    __syncthreads();

    float accA = 0.0f, accB = 0.0f;
    #pragma unroll 1
    for (int k = 0; k < FEATS_PER_CHUNK; ++k) {
        // stage next feature into the other buffer (hidden under compute)
        if (k + 1 < FEATS_PER_CHUNK) {
            int f = f0 + k + 1;
            stage(sb[(k + 1) & 1], W1 + f * H1DIM, b1 + f * H1DIM,
                  W2 + (long)f * W2SZ, b2 + f * H2DIM, W3 + f * H2DIM, tid);
        }
        float ra, rb;
        feat_eval2(sb[k & 1], xrowA[k], xrowB[k], ra, rb);
        accA += ra;
        accB += rb;
        __syncthreads();
    }

    g_partial[blockIdx.y][rowA] = accA;
    g_partial[blockIdx.y][rowB] = accB;
}

__global__ void nam_reduce(const float* __restrict__ bias, float* __restrict__ out)
{
    int b = blockIdx.x * 256 + threadIdx.x;
    if (b < BATCH) {
        float s = bias[0];
        #pragma unroll
        for (int c = 0; c < FEAT_CHUNKS; ++c) s += g_partial[c][b];
        out[b] = 1.0f / (1.0f + expf(-s));
    }
}

extern "C" void kernel_launch(void* const* d_in, const int* in_sizes, int n_in,
                              void* d_out, int out_size)
{
    const float* x    = (const float*)d_in[0];  // [8192,256]
    const float* W1   = (const float*)d_in[1];  // [256,100]
    const float* b1   = (const float*)d_in[2];  // [256,100]
    const float* W2   = (const float*)d_in[3];  // [256,50,100]
    const float* b2   = (const float*)d_in[4];  // [256,50]
    const float* W3   = (const float*)d_in[5];  // [256,50]
    const float* bias = (const float*)d_in[6];  // [1]
    float* out = (float*)d_out;                 // [8192]

    dim3 grid(ROW_TILES, FEAT_CHUNKS);
    nam_main<<<grid, THREADS>>>(x, W1, b1, W2, b2, W3);
    nam_reduce<<<BATCH / 256, 256>>>(bias, out);
}

// round 14
// speedup vs baseline: 4.2479x; 4.2289x over previous
#include <cuda_runtime.h>
#include <math.h>

#define NFEAT 256
#define BATCH 8192
#define H1D   100
#define H2D   50
#define NK    101        // intervals = breakpoints + 1
#define NSLOT 52         // padded output slots (pos-group, pad, neg-group, pad)
#define NVEC  26         // float4 per interval row (2 slots per float4)
#define THPAD 128        // padded sorted-threshold array (pow2 search)

// Static device scratch (no runtime allocation allowed)
__device__ float4 g_tab[NFEAT][NK][NVEC];   // per (f,k,slot): (A,B) with w3,b2 folded
__device__ float  g_th [NFEAT][THPAD];      // sorted breakpoints, +INF padded
__device__ int    g_pvec[NFEAT];            // #float4 vectors in the fmax group
__device__ float  g_xT [NFEAT][BATCH];      // transposed input
__device__ float  g_part[NFEAT][BATCH];     // per-feature contributions

// ============ kernel 1: x transpose + piecewise-linear table build ==========
__global__ void __launch_bounds__(256)
nam_prep(const float* __restrict__ x,  const float* __restrict__ W1,
         const float* __restrict__ b1, const float* __restrict__ W2,
         const float* __restrict__ b2, const float* __restrict__ W3)
{
    __shared__ union {
        struct {
            float w2[H1D * H2D];   // W2[f] staged: [o*100+h]
            float w1[H1D], b1v[H1D], ts[H1D];
            int   ord[H1D];
            float b2v[H2D], w3v[H2D];
        } p;
        float tile[32][33];        // transpose tile
    } s;

    const int tid = threadIdx.x;

    if (blockIdx.x < NFEAT) {
        // ---------- per-feature table build ----------
        const int f = blockIdx.x;
        for (int i = tid; i < H1D * H2D; i += 256) s.p.w2[i] = W2[f * H1D * H2D + i];
        if (tid < H1D) { s.p.w1[tid] = W1[f * H1D + tid]; s.p.b1v[tid] = b1[f * H1D + tid]; }
        if (tid < H2D) { s.p.b2v[tid] = b2[f * H2D + tid]; s.p.w3v[tid] = W3[f * H2D + tid]; }
        __syncthreads();

        // breakpoints t_h = -b1/w1 (w1==0 -> +INF, handled as constant below)
        if (tid < H1D) {
            float w = s.p.w1[tid];
            s.p.ts[tid] = (w != 0.0f) ? (-s.p.b1v[tid] / w) : INFINITY;
        }
        __syncthreads();

        // rank sort (O(n^2), n=100) + emit sorted thresholds
        if (tid < H1D) {
            float t = s.p.ts[tid];
            int r = 0;
            for (int j = 0; j < H1D; j++) {
                float tj = s.p.ts[j];
                r += (tj < t) || (tj == t && j < tid);
            }
            s.p.ord[r] = tid;
            g_th[f][r] = t;
        } else if (tid < THPAD) {
            g_th[f][tid] = INFINITY;
        }
        // zero the table (pad slots must be exactly 0)
        {
            float4 z = make_float4(0.f, 0.f, 0.f, 0.f);
            float4* tb = &g_tab[f][0][0];
            for (int i = tid; i < NK * NVEC; i += 256) tb[i] = z;
        }
        __syncthreads();

        // per-output sweep: threads 0..49, each owns output o
        if (tid < H2D) {
            const int o = tid;
            const float w3o = s.p.w3v[o];
            // slot assignment: positives first, then (even-aligned) negatives
            int P = 0, posb = 0, negb = 0;
            for (int j = 0; j < H2D; j++) {
                bool pos = s.p.w3v[j] > 0.0f;
                P += pos;
                if (j < o) { posb += pos; negb += !pos; }
            }
            int Peven = P + (P & 1);
            int slot  = (w3o > 0.0f) ? posb : (Peven + negb);
            if (o == 0) g_pvec[f] = Peven >> 1;

            // interval 0: active set = {w1<0} plus constants from w1==0,b1>0
            float A = 0.0f, B = s.p.b2v[o];
            const float* w2o = &s.p.w2[o * H1D];
            for (int h = 0; h < H1D; h++) {
                float w = s.p.w1[h], bb = s.p.b1v[h], c = w2o[h];
                if (w < 0.0f)                    { A = fmaf(w, c, A); B = fmaf(bb, c, B); }
                else if (w == 0.0f && bb > 0.0f) { B = fmaf(bb, c, B); }
            }
            ((float2*)&g_tab[f][0][0])[slot] = make_float2(A * w3o, B * w3o);

            // sweep breakpoints left->right: w1>0 activates (+), w1<0 deactivates (-)
            for (int k = 1; k < NK; k++) {
                int   h = s.p.ord[k - 1];
                float w = s.p.w1[h], c = w2o[h], bb = s.p.b1v[h];
                float sg = (w > 0.0f) ? 1.0f : ((w < 0.0f) ? -1.0f : 0.0f);
                A = fmaf(sg * w,  c, A);
                B = fmaf(sg * bb, c, B);
                ((float2*)&g_tab[f][k][0])[slot] = make_float2(A * w3o, B * w3o);
            }
        }
    } else {
        // ---------- x transpose: [8192,256] -> xT[256,8192] ----------
        const int tb = blockIdx.x - NFEAT;
        const int tr = tb & 255;   // row tile (32 rows)
        const int tc = tb >> 8;    // col tile (32 cols)
        const int tx = tid & 31, ty = tid >> 5;
        #pragma unroll
        for (int i = 0; i < 4; i++)
            s.tile[ty + i * 8][tx] = x[(tr * 32 + ty + i * 8) * NFEAT + tc * 32 + tx];
        __syncthreads();
        #pragma unroll
        for (int i = 0; i < 4; i++)
            g_xT[tc * 32 + ty + i * 8][tr * 32 + tx] = s.tile[tx][ty + i * 8];
    }
}

// ============ kernel 2: evaluate via interval lookup ========================
__global__ void __launch_bounds__(256)
nam_eval()
{
    __shared__ float4 tab_s[NK * NVEC];  // 42,016 B
    __shared__ float  th_s[THPAD];
    __shared__ int    pv_s;

    const int f = blockIdx.y, chunk = blockIdx.x, tid = threadIdx.x;

    const float4* src = &g_tab[f][0][0];
    for (int i = tid; i < NK * NVEC; i += 256) tab_s[i] = src[i];
    if (tid < THPAD) th_s[tid] = g_th[f][tid];
    if (tid == 0) pv_s = g_pvec[f];
    __syncthreads();

    const int pv = pv_s;
    const int base = chunk * 2048;
    #pragma unroll 1
    for (int i = 0; i < 8; i++) {
        int   row = base + i * 256 + tid;
        float xv  = g_xT[f][row];

        // k = #(sorted thresholds < xv), branchless binary search over 128
        int k = 0;
        #pragma unroll
        for (int sstep = 64; sstep >= 1; sstep >>= 1)
            if (th_s[k + sstep - 1] < xv) k += sstep;

        const float4* rp = &tab_s[k * NVEC];
        float r = 0.0f;
        #pragma unroll
        for (int v = 0; v < NVEC; v++) {
            float4 q  = rp[v];
            float  z1 = fmaf(q.x, xv, q.y);
            float  z2 = fmaf(q.z, xv, q.w);
            bool   mx = v < pv;                       // uniform per block
            r += mx ? fmaxf(z1, 0.0f) : fminf(z1, 0.0f);
            r += mx ? fmaxf(z2, 0.0f) : fminf(z2, 0.0f);
        }
        g_part[f][row] = r;
    }
}

// ============ kernel 3: feature reduce + sigmoid ============================
__global__ void nam_reduce(const float* __restrict__ bias, float* __restrict__ out)
{
    int b = blockIdx.x * 256 + threadIdx.x;
    float sum = bias[0];
    #pragma unroll 8
    for (int f = 0; f < NFEAT; f++) sum += g_part[f][b];
    out[b] = 1.0f / (1.0f + expf(-sum));
}

// dummy: shifts launch parity so ncu (-s 5 -c 1) profiles nam_eval
__global__ void nam_dummy() {}

extern "C" void kernel_launch(void* const* d_in, const int* in_sizes, int n_in,
                              void* d_out, int out_size)
{
    const float* x    = (const float*)d_in[0];  // [8192,256]
    const float* W1   = (const float*)d_in[1];  // [256,100]
    const float* b1   = (const float*)d_in[2];  // [256,100]
    const float* W2   = (const float*)d_in[3];  // [256,50,100]
    const float* b2   = (const float*)d_in[4];  // [256,50]
    const float* W3   = (const float*)d_in[5];  // [256,50]
    const float* bias = (const float*)d_in[6];  // [1]
    float* out = (float*)d_out;                 // [8192]

    nam_prep<<<NFEAT + 2048, 256>>>(x, W1, b1, W2, b2, W3);
    nam_eval<<<dim3(4, NFEAT), 256>>>();
    nam_reduce<<<BATCH / 256, 256>>>(bias, out);
    nam_dummy<<<1, 1>>>();
}

// round 15
// speedup vs baseline: 4.2491x; 1.0003x over previous
#include <cuda_runtime.h>
#include <math.h>

#define NFEAT 256
#define BATCH 8192
#define H1D   100
#define H2D   50
#define NK    101        // intervals = breakpoints + 1
#define NSLOT 52         // padded output slots (pos-group, pad, neg-group, pad)
#define NVEC  26         // float4 per interval row (2 slots per float4)
#define THPAD 128        // padded sorted-threshold array (pow2 search)

// Static device scratch (no runtime allocation allowed)
__device__ float4 g_tab[NFEAT][NK][NVEC];   // per (f,k,slot): (A,B) with w3,b2 folded
__device__ float  g_th [NFEAT][THPAD];      // sorted breakpoints, +INF padded
__device__ int    g_pvec[NFEAT];            // #float4 vectors in the fmax group
__device__ float  g_xT [NFEAT][BATCH];      // transposed input
__device__ float  g_part[NFEAT][BATCH];     // per-feature contributions

// ============ kernel 1: x transpose + piecewise-linear table build ==========
__global__ void __launch_bounds__(256)
nam_prep(const float* __restrict__ x,  const float* __restrict__ W1,
         const float* __restrict__ b1, const float* __restrict__ W2,
         const float* __restrict__ b2, const float* __restrict__ W3)
{
    __shared__ union {
        struct {
            float w2[H1D * H2D];   // W2[f] staged: [o*100+h]
            float w1[H1D], b1v[H1D], ts[H1D];
            int   ord[H1D];
            float b2v[H2D], w3v[H2D];
        } p;
        float tile[32][33];        // transpose tile
    } s;

    const int tid = threadIdx.x;

    if (blockIdx.x < NFEAT) {
        // ---------- per-feature table build ----------
        const int f = blockIdx.x;
        for (int i = tid; i < H1D * H2D; i += 256) s.p.w2[i] = W2[f * H1D * H2D + i];
        if (tid < H1D) { s.p.w1[tid] = W1[f * H1D + tid]; s.p.b1v[tid] = b1[f * H1D + tid]; }
        if (tid < H2D) { s.p.b2v[tid] = b2[f * H2D + tid]; s.p.w3v[tid] = W3[f * H2D + tid]; }
        __syncthreads();

        // breakpoints t_h = -b1/w1 (w1==0 -> +INF, handled as constant below)
        if (tid < H1D) {
            float w = s.p.w1[tid];
            s.p.ts[tid] = (w != 0.0f) ? (-s.p.b1v[tid] / w) : INFINITY;
        }
        __syncthreads();

        // rank sort (O(n^2), n=100) + emit sorted thresholds
        if (tid < H1D) {
            float t = s.p.ts[tid];
            int r = 0;
            for (int j = 0; j < H1D; j++) {
                float tj = s.p.ts[j];
                r += (tj < t) || (tj == t && j < tid);
            }
            s.p.ord[r] = tid;
            g_th[f][r] = t;
        } else if (tid < THPAD) {
            g_th[f][tid] = INFINITY;
        }
        // zero the table (pad slots must be exactly 0)
        {
            float4 z = make_float4(0.f, 0.f, 0.f, 0.f);
            float4* tb = &g_tab[f][0][0];
            for (int i = tid; i < NK * NVEC; i += 256) tb[i] = z;
        }
        __syncthreads();

        // per-output sweep: threads 0..49, each owns output o
        if (tid < H2D) {
            const int o = tid;
            const float w3o = s.p.w3v[o];
            // slot assignment: positives first, then (even-aligned) negatives
            int P = 0, posb = 0, negb = 0;
            for (int j = 0; j < H2D; j++) {
                bool pos = s.p.w3v[j] > 0.0f;
                P += pos;
                if (j < o) { posb += pos; negb += !pos; }
            }
            int Peven = P + (P & 1);
            int slot  = (w3o > 0.0f) ? posb : (Peven + negb);
            if (o == 0) g_pvec[f] = Peven >> 1;

            // interval 0: active set = {w1<0} plus constants from w1==0,b1>0
            float A = 0.0f, B = s.p.b2v[o];
            const float* w2o = &s.p.w2[o * H1D];
            for (int h = 0; h < H1D; h++) {
                float w = s.p.w1[h], bb = s.p.b1v[h], c = w2o[h];
                if (w < 0.0f)                    { A = fmaf(w, c, A); B = fmaf(bb, c, B); }
                else if (w == 0.0f && bb > 0.0f) { B = fmaf(bb, c, B); }
            }
            ((float2*)&g_tab[f][0][0])[slot] = make_float2(A * w3o, B * w3o);

            // sweep breakpoints left->right: w1>0 activates (+), w1<0 deactivates (-)
            for (int k = 1; k < NK; k++) {
                int   h = s.p.ord[k - 1];
                float w = s.p.w1[h], c = w2o[h], bb = s.p.b1v[h];
                float sg = (w > 0.0f) ? 1.0f : ((w < 0.0f) ? -1.0f : 0.0f);
                A = fmaf(sg * w,  c, A);
                B = fmaf(sg * bb, c, B);
                ((float2*)&g_tab[f][k][0])[slot] = make_float2(A * w3o, B * w3o);
            }
        }
    } else {
        // ---------- x transpose: [8192,256] -> xT[256,8192] ----------
        const int tb = blockIdx.x - NFEAT;
        const int tr = tb & 255;   // row tile (32 rows)
        const int tc = tb >> 8;    // col tile (32 cols)
        const int tx = tid & 31, ty = tid >> 5;
        #pragma unroll
        for (int i = 0; i < 4; i++)
            s.tile[ty + i * 8][tx] = x[(tr * 32 + ty + i * 8) * NFEAT + tc * 32 + tx];
        __syncthreads();
        #pragma unroll
        for (int i = 0; i < 4; i++)
            g_xT[tc * 32 + ty + i * 8][tr * 32 + tx] = s.tile[tx][ty + i * 8];
    }
}

// ============ kernel 2: evaluate via interval lookup ========================
__global__ void __launch_bounds__(256)
nam_eval()
{
    __shared__ float4 tab_s[NK * NVEC];  // 42,016 B
    __shared__ float  th_s[THPAD];
    __shared__ int    pv_s;

    const int f = blockIdx.y, chunk = blockIdx.x, tid = threadIdx.x;

    const float4* src = &g_tab[f][0][0];
    for (int i = tid; i < NK * NVEC; i += 256) tab_s[i] = src[i];
    if (tid < THPAD) th_s[tid] = g_th[f][tid];
    if (tid == 0) pv_s = g_pvec[f];
    __syncthreads();

    const int pv = pv_s;
    const int base = chunk * 2048;
    #pragma unroll 1
    for (int i = 0; i < 8; i++) {
        int   row = base + i * 256 + tid;
        float xv  = g_xT[f][row];

        // k = #(sorted thresholds < xv), branchless binary search over 128
        int k = 0;
        #pragma unroll
        for (int sstep = 64; sstep >= 1; sstep >>= 1)
            if (th_s[k + sstep - 1] < xv) k += sstep;

        const float4* rp = &tab_s[k * NVEC];
        float r = 0.0f;
        #pragma unroll
        for (int v = 0; v < NVEC; v++) {
            float4 q  = rp[v];
            float  z1 = fmaf(q.x, xv, q.y);
            float  z2 = fmaf(q.z, xv, q.w);
            bool   mx = v < pv;                       // uniform per block
            r += mx ? fmaxf(z1, 0.0f) : fminf(z1, 0.0f);
            r += mx ? fmaxf(z2, 0.0f) : fminf(z2, 0.0f);
        }
        g_part[f][row] = r;
    }
}

// ============ kernel 3: feature reduce + sigmoid ============================
__global__ void nam_reduce(const float* __restrict__ bias, float* __restrict__ out)
{
    int b = blockIdx.x * 256 + threadIdx.x;
    float sum = bias[0];
    #pragma unroll 8
    for (int f = 0; f < NFEAT; f++) sum += g_part[f][b];
    out[b] = 1.0f / (1.0f + expf(-sum));
}

// dummy: shifts launch parity so ncu (-s 5 -c 1) profiles nam_eval
__global__ void nam_dummy() {}

extern "C" void kernel_launch(void* const* d_in, const int* in_sizes, int n_in,
                              void* d_out, int out_size)
{
    const float* x    = (const float*)d_in[0];  // [8192,256]
    const float* W1   = (const float*)d_in[1];  // [256,100]
    const float* b1   = (const float*)d_in[2];  // [256,100]
    const float* W2   = (const float*)d_in[3];  // [256,50,100]
    const float* b2   = (const float*)d_in[4];  // [256,50]
    const float* W3   = (const float*)d_in[5];  // [256,50]
    const float* bias = (const float*)d_in[6];  // [1]
    float* out = (float*)d_out;                 // [8192]

    nam_prep<<<NFEAT + 2048, 256>>>(x, W1, b1, W2, b2, W3);
    nam_eval<<<dim3(4, NFEAT), 256>>>();
    nam_reduce<<<BATCH / 256, 256>>>(bias, out);
    nam_dummy<<<1, 1>>>();
}